// round 13
// baseline (speedup 1.0000x reference)
#include <cuda_runtime.h>
#include <cuda_fp16.h>
#include <mma.h>
#include <cstdint>

using namespace nvcuda;

// Shapes
#define B_  4
#define S_  1024
#define D_  2048
#define H_  16
#define HD_ 128
#define RD_ 64
#define NT  (B_*S_)      // 4096 tokens
#define D3  (3*D_)       // 6144
#define KC  8            // mod-gemm split-K chunks

// ---------------- scratch (static device arrays; allocation-free) -------------
__device__ float  g_m3p[KC*B_*D3];
__device__ float  g_m3[B_*D3];
__device__ __half g_xnh[(size_t)NT*D_];
__device__ float  g_qkv[(size_t)NT*D3];
__device__ __half g_qh[(size_t)B_*H_*S_*HD_];
__device__ __half g_kh[(size_t)B_*H_*S_*HD_];
__device__ __half g_vh[(size_t)B_*H_*S_*HD_];
__device__ __half g_sh[(size_t)B_*H_*S_*S_];   // 128 MB exp(scores-2)
__device__ __half g_oh[(size_t)NT*D_];
__device__ float  g_t[(size_t)NT*D_];          // out-proj f32 result
__device__ __half g_qkvwh[(size_t)D_*D3];      // fp16 qkv_w
__device__ __half g_outwh[(size_t)D_*D_];      // fp16 out_w

// ---------------- cp.async helpers -------------------------------------------
__device__ __forceinline__ void cp_async16(void* smem_dst, const void* gmem_src) {
    uint32_t s = (uint32_t)__cvta_generic_to_shared(smem_dst);
    asm volatile("cp.async.cg.shared.global [%0], [%1], 16;\n" :: "r"(s), "l"(gmem_src));
}
__device__ __forceinline__ void cp_commit() {
    asm volatile("cp.async.commit_group;\n" ::: "memory");
}
__device__ __forceinline__ void cp_wait1() {
    asm volatile("cp.async.wait_group 1;\n" ::: "memory");
}

// ---------------- helpers ----------------------------------------------------
template<int NW>
__device__ __forceinline__ float block_sum(float v, float* sh) {
    #pragma unroll
    for (int o = 16; o > 0; o >>= 1) v += __shfl_xor_sync(0xffffffffu, v, o);
    int w = threadIdx.x >> 5;
    if ((threadIdx.x & 31) == 0) sh[w] = v;
    __syncthreads();
    float r = 0.f;
    #pragma unroll
    for (int i = 0; i < NW; i++) r += sh[i];
    __syncthreads();
    return r;
}

// ---------------- K0: round weights to fp16 scratch ---------------------------
__global__ void k_round_h(const float* __restrict__ in, __half* __restrict__ o) {
    int i = blockIdx.x * 256 + threadIdx.x;
    float4 v = reinterpret_cast<const float4*>(in)[i];
    __half2* o2 = reinterpret_cast<__half2*>(o);
    o2[2*i]   = __floats2half2_rn(v.x, v.y);
    o2[2*i+1] = __floats2half2_rn(v.z, v.w);
}

// ---------------- K1: mod GEMM (split-K partials, deterministic) --------------
__global__ void k_mod_part(const float* __restrict__ mod,
                           const float* __restrict__ mod_w) {
    __shared__ float sm[B_*256];
    int kc = blockIdx.y;
    int k0 = kc * 256;
    for (int i = threadIdx.x; i < B_*256; i += blockDim.x)
        sm[i] = mod[(i >> 8) * D_ + k0 + (i & 255)];
    __syncthreads();
    int j = blockIdx.x * 128 + threadIdx.x;
    float a0=0.f, a1=0.f, a2=0.f, a3=0.f;
    #pragma unroll 4
    for (int k = 0; k < 256; k++) {
        float w = mod_w[(size_t)(k0 + k) * D3 + j];
        a0 = fmaf(sm[k],       w, a0);
        a1 = fmaf(sm[256 + k], w, a1);
        a2 = fmaf(sm[512 + k], w, a2);
        a3 = fmaf(sm[768 + k], w, a3);
    }
    float* p = g_m3p + (size_t)kc * (B_*D3);
    p[0*D3 + j] = a0; p[1*D3 + j] = a1; p[2*D3 + j] = a2; p[3*D3 + j] = a3;
}

__global__ void k_mod_red(const float* __restrict__ mod_b) {
    int i = blockIdx.x * 256 + threadIdx.x;
    float s = 0.f;
    #pragma unroll
    for (int c = 0; c < KC; c++) s += g_m3p[c * (B_*D3) + i];
    g_m3[i] = s + mod_b[i % D3];
}

// ---------------- K2: LayerNorm + AdaLN modulation (fp16 out) -----------------
__global__ void k_lnmod(const float* __restrict__ x) {
    __shared__ float sh[8];
    int m = blockIdx.x;       // token
    int b = m >> 10;
    int t = threadIdx.x;
    const float* xr = x + (size_t)m * D_;
    float4 v0 = *reinterpret_cast<const float4*>(xr + t*4);
    float4 v1 = *reinterpret_cast<const float4*>(xr + 1024 + t*4);
    float s = v0.x+v0.y+v0.z+v0.w + v1.x+v1.y+v1.z+v1.w;
    s = block_sum<8>(s, sh);
    float mean = s * (1.f / D_);
    float d0=v0.x-mean, d1=v0.y-mean, d2=v0.z-mean, d3=v0.w-mean;
    float d4=v1.x-mean, d5=v1.y-mean, d6=v1.z-mean, d7=v1.w-mean;
    float ss = d0*d0+d1*d1+d2*d2+d3*d3+d4*d4+d5*d5+d6*d6+d7*d7;
    ss = block_sum<8>(ss, sh);
    float rinv = rsqrtf(ss * (1.f / D_) + 1e-6f);
    const float* mb  = g_m3 + b * D3;        // bias
    const float* msc = mb + D_;              // scale
    int e0 = t*4, e1 = 1024 + t*4;
    float o0 = d0*rinv*(1.f+msc[e0+0]) + mb[e0+0];
    float o1 = d1*rinv*(1.f+msc[e0+1]) + mb[e0+1];
    float o2 = d2*rinv*(1.f+msc[e0+2]) + mb[e0+2];
    float o3 = d3*rinv*(1.f+msc[e0+3]) + mb[e0+3];
    float o4 = d4*rinv*(1.f+msc[e1+0]) + mb[e1+0];
    float o5 = d5*rinv*(1.f+msc[e1+1]) + mb[e1+1];
    float o6 = d6*rinv*(1.f+msc[e1+2]) + mb[e1+2];
    float o7 = d7*rinv*(1.f+msc[e1+3]) + mb[e1+3];
    __half* xo = g_xnh + (size_t)m * D_;
    *reinterpret_cast<__half2*>(xo + e0)     = __floats2half2_rn(o0, o1);
    *reinterpret_cast<__half2*>(xo + e0 + 2) = __floats2half2_rn(o2, o3);
    *reinterpret_cast<__half2*>(xo + e1)     = __floats2half2_rn(o4, o5);
    *reinterpret_cast<__half2*>(xo + e1 + 2) = __floats2half2_rn(o6, o7);
}

// ---------------- fp16 WMMA GEMM, 3-stage, BK=64, ONE sync per tile -----------
// 128x128 tile, 4 warps of 64x64. !SUMR: C(f32) = A*B.
// SUMR (PV path): also accumulate row sums of A; epilogue writes fp16 Oh = acc/l.
template<bool SUMR>
__global__ void __launch_bounds__(128, 2)
k_gemm3h(const __half* __restrict__ A, int lda, long long sA1, long long sA2,
         const __half* __restrict__ B, int ldb, long long sB1, long long sB2,
         float*  __restrict__ C, __half* __restrict__ Oh,
         int ldc, long long sC1, long long sC2,
         int K, int zdiv) {
    constexpr int BM = 128, BN = 128, BK = 64;
    constexpr int AKP = BK + 8;    // 72 halves/row (144 B)
    constexpr int BNP = BN + 8;    // 136 halves/row (272 B)
    constexpr int AS_SZ = BM * AKP;    // 9216 halves
    constexpr int BS_SZ = BK * BNP;    // 8704 halves
    constexpr int STG = AS_SZ + BS_SZ; // 17920 halves per stage
    extern __shared__ __align__(16) char smraw[];
    __half* smem = reinterpret_cast<__half*>(smraw);
    float* scr  = reinterpret_cast<float*>(smraw + 3 * STG * 2);  // 4w x 320 f32
    float* srow = scr + 4 * 320;                                  // 128 f32

    int z  = blockIdx.z;
    int z1 = z / zdiv, z2 = z - z1 * zdiv;
    A += (size_t)(z1 * sA1 + z2 * sA2);
    B += (size_t)(z1 * sB1 + z2 * sB2);
    if (SUMR) Oh += (size_t)(z1 * sC1 + z2 * sC2);
    else      C  += (size_t)(z1 * sC1 + z2 * sC2);

    int tid = threadIdx.x;
    int wid = tid >> 5, lane = tid & 31;
    int wm = wid & 1, wn = wid >> 1;          // 2x2 warps of 64x64
    int bm0 = blockIdx.y * BM, bn0 = blockIdx.x * BN;

    auto load_stage = [&](int kt, int s) {
        __half* As = smem + s * STG;
        __half* Bs = As + AS_SZ;
        #pragma unroll
        for (int it = 0; it < 8; it++) {      // A: 128 rows x 64 halves
            int idx = tid + it * 128;
            int r = idx >> 3, c = (idx & 7) << 3;
            cp_async16(&As[r * AKP + c],
                       A + (size_t)(bm0 + r) * lda + kt + c);
        }
        #pragma unroll
        for (int it = 0; it < 8; it++) {      // B: 64(k) x 128(n) halves
            int idx = tid + it * 128;
            int r = idx >> 4, c = (idx & 15) << 3;
            cp_async16(&Bs[r * BNP + c],
                       B + (size_t)(kt + r) * ldb + bn0 + c);
        }
    };

    wmma::fragment<wmma::accumulator, 16, 16, 16, float> acc[4][4];
    #pragma unroll
    for (int i = 0; i < 4; i++)
        #pragma unroll
        for (int j = 0; j < 4; j++) wmma::fill_fragment(acc[i][j], 0.0f);

    float lsum = 0.f;
    int T = K / BK;
    load_stage(0, 0);  cp_commit();
    load_stage(BK, 1); cp_commit();

    int sbuf = 0;       // stage of tile t (t % 3)
    for (int t = 0; t < T; t++) {
        cp_wait1();                     // tile t landed
        __syncthreads();                // visibility + everyone done with t-1
        int nt = t + 2;
        if (nt < T) {
            int ns = sbuf + 2; if (ns >= 3) ns -= 3;
            load_stage(nt * BK, ns);
            cp_commit();
        }
        __half* As = smem + sbuf * STG;
        __half* Bs = As + AS_SZ;
        if (SUMR) {                     // thread r sums row r (rotated access)
            const __half* ar = &As[tid * AKP];
            #pragma unroll
            for (int c = 0; c < BK; c++) lsum += __half2float(ar[(tid + c) & 63]);
        }
        #pragma unroll
        for (int ks = 0; ks < BK; ks += 16) {
            wmma::fragment<wmma::matrix_a, 16, 16, 16, __half, wmma::row_major> af[4];
            #pragma unroll
            for (int i = 0; i < 4; i++)
                wmma::load_matrix_sync(af[i], &As[(wm * 64 + i * 16) * AKP + ks], AKP);
            #pragma unroll
            for (int j = 0; j < 4; j++) {
                wmma::fragment<wmma::matrix_b, 16, 16, 16, __half, wmma::row_major> bf;
                wmma::load_matrix_sync(bf, &Bs[ks * BNP + wn * 64 + j * 16], BNP);
                #pragma unroll
                for (int i = 0; i < 4; i++)
                    wmma::mma_sync(acc[i][j], af[i], bf, acc[i][j]);
            }
        }
        if (++sbuf == 3) sbuf = 0;
    }

    if (SUMR) {
        // fused normalize epilogue: Oh[r, c] = half(acc[r, c] / l[r])
        srow[tid] = lsum;
        __syncthreads();
        float* scrw = scr + wid * 320;   // 16 x 20 f32
        int row = lane >> 1, ch = (lane & 1) * 8;
        #pragma unroll
        for (int i = 0; i < 4; i++) {
            float inv = 1.f / srow[wm * 64 + i * 16 + row];
            #pragma unroll
            for (int j = 0; j < 4; j++) {
                __syncwarp();
                wmma::store_matrix_sync(scrw, acc[i][j], 20, wmma::mem_row_major);
                __syncwarp();
                __align__(16) __half hv[8];
                #pragma unroll
                for (int e = 0; e < 8; e++)
                    hv[e] = __float2half_rn(scrw[row * 20 + ch + e] * inv);
                *reinterpret_cast<uint4*>(
                    &Oh[(size_t)(bm0 + wm * 64 + i * 16 + row) * ldc + bn0 + wn * 64 + j * 16 + ch]) =
                    *reinterpret_cast<uint4*>(hv);
            }
        }
    } else {
        #pragma unroll
        for (int i = 0; i < 4; i++)
            #pragma unroll
            for (int j = 0; j < 4; j++)
                wmma::store_matrix_sync(C + (size_t)(bm0 + wm * 64 + i * 16) * ldc + bn0 + wn * 64 + j * 16,
                                        acc[i][j], ldc, wmma::mem_row_major);
    }
}

static const int SMEM_GH = 3 * 17920 * 2 + (4 * 320 + 128) * 4;  // 113024 bytes

// ---------------- fp16 WMMA GEMM BT + exp epilogue (scores -> E, half) --------
// C[M,N](h) = exp(A[M,K](h) * B[N,K](h)^T - 2); 128x128 tile, 4 warps of 64x64.
__global__ void __launch_bounds__(128, 2)
k_gemmBTexp(const __half* __restrict__ A, int lda, long long sA1,
            const __half* __restrict__ B, int ldb, long long sB1,
            __half*       __restrict__ C, int ldc, long long sC1,
            int K) {
    constexpr int BM = 128, BN = 128, BK = 32;
    constexpr int AKP = BK + 8;        // 40 halves
    constexpr int AS_SZ = BM * AKP;    // 5120 halves
    extern __shared__ __align__(16) char smraw[];
    __half* sh = reinterpret_cast<__half*>(smraw);
    __half* As0 = sh;
    __half* As1 = sh + AS_SZ;
    __half* Bs0 = sh + 2 * AS_SZ;
    __half* Bs1 = sh + 3 * AS_SZ;
    float* scr = reinterpret_cast<float*>(smraw + 4 * AS_SZ * 2);  // 4w x 320 f32

    int z  = blockIdx.z;
    A += (size_t)z * sA1;
    B += (size_t)z * sB1;
    C += (size_t)z * sC1;

    int tid = threadIdx.x;
    int wid = tid >> 5, lane = tid & 31;
    int wm = wid & 1, wn = wid >> 1;
    int bm0 = blockIdx.y * BM, bn0 = blockIdx.x * BN;

    auto load_stage = [&](int kt, int buf) {
        __half* As = buf ? As1 : As0;
        __half* Bs = buf ? Bs1 : Bs0;
        #pragma unroll
        for (int it = 0; it < 4; it++) {
            int idx = tid + it * 128;
            int r = idx >> 2, c = (idx & 3) << 3;
            cp_async16(&As[r * AKP + c],
                       A + (size_t)(bm0 + r) * lda + kt + c);
        }
        #pragma unroll
        for (int it = 0; it < 4; it++) {
            int idx = tid + it * 128;
            int r = idx >> 2, c = (idx & 3) << 3;
            cp_async16(&Bs[r * AKP + c],
                       B + (size_t)(bn0 + r) * ldb + kt + c);
        }
    };

    wmma::fragment<wmma::accumulator, 16, 16, 16, float> acc[4][4];
    #pragma unroll
    for (int i = 0; i < 4; i++)
        #pragma unroll
        for (int j = 0; j < 4; j++) wmma::fill_fragment(acc[i][j], 0.0f);

    int T = K / BK;
    load_stage(0, 0);
    cp_commit();

    for (int t = 0; t < T; t++) {
        if (t + 1 < T) load_stage((t + 1) * BK, (t + 1) & 1);
        cp_commit();
        cp_wait1();
        __syncthreads();
        int buf = t & 1;
        __half* As = buf ? As1 : As0;
        __half* Bs = buf ? Bs1 : Bs0;
        #pragma unroll
        for (int ks = 0; ks < BK; ks += 16) {
            wmma::fragment<wmma::matrix_a, 16, 16, 16, __half, wmma::row_major> af[4];
            #pragma unroll
            for (int i = 0; i < 4; i++)
                wmma::load_matrix_sync(af[i], &As[(wm * 64 + i * 16) * AKP + ks], AKP);
            #pragma unroll
            for (int j = 0; j < 4; j++) {
                wmma::fragment<wmma::matrix_b, 16, 16, 16, __half, wmma::col_major> bf;
                wmma::load_matrix_sync(bf, &Bs[(wn * 64 + j * 16) * AKP + ks], AKP);
                #pragma unroll
                for (int i = 0; i < 4; i++)
                    wmma::mma_sync(acc[i][j], af[i], bf, acc[i][j]);
            }
        }
        __syncthreads();
    }

    // epilogue: per-warp smem staging, exp(x-2), half store
    float* scrw = scr + wid * 320;   // 16 x 20 f32
    int row = lane >> 1, ch = (lane & 1) * 8;
    #pragma unroll
    for (int i = 0; i < 4; i++)
        #pragma unroll
        for (int j = 0; j < 4; j++) {
            __syncwarp();
            wmma::store_matrix_sync(scrw, acc[i][j], 20, wmma::mem_row_major);
            __syncwarp();
            __align__(16) __half hv[8];
            #pragma unroll
            for (int e = 0; e < 8; e++)
                hv[e] = __float2half_rn(__expf(scrw[row * 20 + ch + e] - 2.0f));
            *reinterpret_cast<uint4*>(
                &C[(size_t)(bm0 + wm * 64 + i * 16 + row) * ldc + bn0 + wn * 64 + j * 16 + ch]) =
                *reinterpret_cast<uint4*>(hv);
        }
}

static const int SMEM_BTH = 4 * 5120 * 2 + 4 * 320 * 4;   // 46080

// ---------------- K4: qkv bias + RMSNorm + RoPE -> half [B,H,S,HD] ------------
__global__ void k_qkvpost(const float* __restrict__ qkv_b,
                          const float* __restrict__ cosb,
                          const float* __restrict__ sinb,
                          const float* __restrict__ nqw,
                          const float* __restrict__ nkw) {
    __shared__ float sh4[4];
    __shared__ float bufq[HD_], bufk[HD_];
    int tok = blockIdx.x, h = blockIdx.y, d = threadIdx.x;
    int b = tok >> 10, s = tok & 1023;
    size_t base = (size_t)tok * D3 + h * HD_;
    float qv = g_qkv[base + d]          + qkv_b[h * HD_ + d];
    float kv = g_qkv[base + D_ + d]     + qkv_b[D_ + h * HD_ + d];
    float vv = g_qkv[base + 2*D_ + d]   + qkv_b[2*D_ + h * HD_ + d];
    float sq = block_sum<4>(qv * qv, sh4);
    float sk = block_sum<4>(kv * kv, sh4);
    float rq = rsqrtf(sq * (1.f / HD_) + 1e-6f);
    float rk = rsqrtf(sk * (1.f / HD_) + 1e-6f);
    float qn = qv * rq * nqw[d];
    float kn = kv * rk * nkw[d];
    bufq[d] = qn; bufk[d] = kn;
    __syncthreads();
    float qo = qn, ko = kn;
    if (d < RD_) {
        int i = d >> 1;
        float c  = cosb[s * (RD_/2) + i];
        float sn = sinb[s * (RD_/2) + i];
        if ((d & 1) == 0) { qo = bufq[d] * c - bufq[d+1] * sn;
                            ko = bufk[d] * c - bufk[d+1] * sn; }
        else              { qo = bufq[d-1] * sn + bufq[d] * c;
                            ko = bufk[d-1] * sn + bufk[d] * c; }
    }
    size_t ob = ((size_t)(b * H_ + h) * S_ + s) * HD_ + d;
    g_qh[ob] = __float2half_rn(qo * 0.08838834764831845f);  // 1/sqrt(HD) in Q
    g_kh[ob] = __float2half_rn(ko);
    g_vh[ob] = __float2half_rn(vv);
}

// ---------------- K9: bias + gate + residual ----------------------------------
__global__ void k_final(const float* __restrict__ x,
                        const float* __restrict__ out_b,
                        float* __restrict__ out) {
    size_t idx = ((size_t)blockIdx.x * blockDim.x + threadIdx.x) * 4;
    int n = (int)(idx & (D_ - 1));
    int m = (int)(idx >> 11);
    int b = m >> 10;
    const float* gate = g_m3 + b * D3 + 2 * D_;
    float4 t  = *reinterpret_cast<float4*>(&g_t[idx]);
    float4 xr = *reinterpret_cast<const float4*>(&x[idx]);
    float4 o;
    o.x = (t.x + out_b[n+0]) * gate[n+0] + xr.x;
    o.y = (t.y + out_b[n+1]) * gate[n+1] + xr.y;
    o.z = (t.z + out_b[n+2]) * gate[n+2] + xr.z;
    o.w = (t.w + out_b[n+3]) * gate[n+3] + xr.w;
    *reinterpret_cast<float4*>(&out[idx]) = o;
}

// ---------------- launch ------------------------------------------------------
extern "C" void kernel_launch(void* const* d_in, const int* in_sizes, int n_in,
                              void* d_out, int out_size) {
    const float* x     = (const float*)d_in[0];
    const float* mod   = (const float*)d_in[1];
    const float* cosb  = (const float*)d_in[2];
    const float* sinb  = (const float*)d_in[3];
    const float* qkv_w = (const float*)d_in[4];
    const float* qkv_b = (const float*)d_in[5];
    const float* mod_w = (const float*)d_in[6];
    const float* mod_b = (const float*)d_in[7];
    const float* out_w = (const float*)d_in[8];
    const float* out_b = (const float*)d_in[9];
    const float* nqw   = (const float*)d_in[10];
    const float* nkw   = (const float*)d_in[11];
    float* out = (float*)d_out;

    __half *p_xnh, *p_qh, *p_kh, *p_vh, *p_sh, *p_oh, *p_qkvwh, *p_outwh;
    float *p_qkv, *p_t;
    cudaGetSymbolAddress((void**)&p_xnh, g_xnh);
    cudaGetSymbolAddress((void**)&p_qkv, g_qkv);
    cudaGetSymbolAddress((void**)&p_qh, g_qh);
    cudaGetSymbolAddress((void**)&p_kh, g_kh);
    cudaGetSymbolAddress((void**)&p_vh, g_vh);
    cudaGetSymbolAddress((void**)&p_sh, g_sh);
    cudaGetSymbolAddress((void**)&p_oh, g_oh);
    cudaGetSymbolAddress((void**)&p_t, g_t);
    cudaGetSymbolAddress((void**)&p_qkvwh, g_qkvwh);
    cudaGetSymbolAddress((void**)&p_outwh, g_outwh);

    cudaFuncSetAttribute(k_gemm3h<false>, cudaFuncAttributeMaxDynamicSharedMemorySize, SMEM_GH);
    cudaFuncSetAttribute(k_gemm3h<true>,  cudaFuncAttributeMaxDynamicSharedMemorySize, SMEM_GH);
    cudaFuncSetAttribute(k_gemmBTexp, cudaFuncAttributeMaxDynamicSharedMemorySize, SMEM_BTH);

    // 0) round the big weights to fp16 scratch
    k_round_h<<<(D_*D3)/(4*256), 256>>>(qkv_w, p_qkvwh);
    k_round_h<<<(D_*D_)/(4*256), 256>>>(out_w, p_outwh);
    // 1) m3 = mod @ mod_w + mod_b  (f32 path)
    k_mod_part<<<dim3(D3/128, KC), 128>>>(mod, mod_w);
    k_mod_red<<<(B_*D3)/256, 256>>>(mod_b);
    // 2) xn = modulate(layernorm(x)) -> fp16
    k_lnmod<<<NT, 256>>>(x);
    // 3) qkv = xn @ qkv_w  (fp16 GEMM BK=64, f32 out; bias folded into K4)
    k_gemm3h<false><<<dim3(D3/128, NT/128), 128, SMEM_GH>>>(
        p_xnh, D_, 0, 0, p_qkvwh, D3, 0, 0, p_qkv, nullptr, D3, 0, 0, D_, 1);
    // 4) bias + rmsnorm + rope -> q,k,v fp16 [B,H,S,HD]
    k_qkvpost<<<dim3(NT, H_), HD_>>>(qkv_b, cosb, sinb, nqw, nkw);
    // 5) E = exp(Q @ K^T - 2) fp16 (bounded: |s|<=11.33 -> E<=1.2e4 < 65504)
    k_gemmBTexp<<<dim3(S_/128, S_/128, B_*H_), 128, SMEM_BTH>>>(
        p_qh, HD_, (long long)S_*HD_,
        p_kh, HD_, (long long)S_*HD_,
        p_sh, S_,  (long long)S_*S_, HD_);
    // 6) O = (E @ V) / rowsum(E) -> fp16 g_oh [B,S,H*HD]; fused normalize
    k_gemm3h<true><<<dim3(1, S_/128, B_*H_), 128, SMEM_GH>>>(
        p_sh, S_,  (long long)H_*S_*S_,  (long long)S_*S_,
        p_vh, HD_, (long long)H_*S_*HD_, (long long)S_*HD_,
        nullptr, p_oh, D_, (long long)S_*D_, (long long)HD_, S_, H_);
    // 7) t = O @ out_w  (fp16 GEMM BK=64, f32 out)
    k_gemm3h<false><<<dim3(D_/128, NT/128), 128, SMEM_GH>>>(
        p_oh, D_, 0, 0, p_outwh, D_, 0, 0, p_t, nullptr, D_, 0, 0, D_, 1);
    // 8) out = (t + out_b) * gate + x
    k_final<<<(NT*D_)/(4*256), 256>>>(x, out_b, out);
}

// round 14
// speedup vs baseline: 1.0434x; 1.0434x over previous
#include <cuda_runtime.h>
#include <cuda_fp16.h>
#include <mma.h>
#include <cstdint>

using namespace nvcuda;

// Shapes
#define B_  4
#define S_  1024
#define D_  2048
#define H_  16
#define HD_ 128
#define RD_ 64
#define NT  (B_*S_)      // 4096 tokens
#define D3  (3*D_)       // 6144
#define KC  8            // mod-gemm split-K chunks

// ---------------- scratch (static device arrays; allocation-free) -------------
__device__ float  g_m3p[KC*B_*D3];
__device__ float  g_m3[B_*D3];
__device__ __half g_xnh[(size_t)NT*D_];
__device__ float  g_qkv[(size_t)NT*D3];
__device__ __half g_qh[(size_t)B_*H_*S_*HD_];
__device__ __half g_kh[(size_t)B_*H_*S_*HD_];
__device__ __half g_vh[(size_t)B_*H_*S_*HD_];
__device__ __half g_sh[(size_t)B_*H_*S_*S_];   // 128 MB exp(scores-2)
__device__ __half g_oh[(size_t)NT*D_];
__device__ __half g_qkvwh[(size_t)D_*D3];      // fp16 qkv_w
__device__ __half g_outwh[(size_t)D_*D_];      // fp16 out_w

// ---------------- cp.async helpers -------------------------------------------
__device__ __forceinline__ void cp_async16(void* smem_dst, const void* gmem_src) {
    uint32_t s = (uint32_t)__cvta_generic_to_shared(smem_dst);
    asm volatile("cp.async.cg.shared.global [%0], [%1], 16;\n" :: "r"(s), "l"(gmem_src));
}
__device__ __forceinline__ void cp_commit() {
    asm volatile("cp.async.commit_group;\n" ::: "memory");
}
__device__ __forceinline__ void cp_wait1() {
    asm volatile("cp.async.wait_group 1;\n" ::: "memory");
}

// ---------------- helpers ----------------------------------------------------
template<int NW>
__device__ __forceinline__ float block_sum(float v, float* sh) {
    #pragma unroll
    for (int o = 16; o > 0; o >>= 1) v += __shfl_xor_sync(0xffffffffu, v, o);
    int w = threadIdx.x >> 5;
    if ((threadIdx.x & 31) == 0) sh[w] = v;
    __syncthreads();
    float r = 0.f;
    #pragma unroll
    for (int i = 0; i < NW; i++) r += sh[i];
    __syncthreads();
    return r;
}

// ---------------- K0: round weights to fp16 scratch ---------------------------
__global__ void k_round_h(const float* __restrict__ in, __half* __restrict__ o) {
    int i = blockIdx.x * 256 + threadIdx.x;
    float4 v = reinterpret_cast<const float4*>(in)[i];
    __half2* o2 = reinterpret_cast<__half2*>(o);
    o2[2*i]   = __floats2half2_rn(v.x, v.y);
    o2[2*i+1] = __floats2half2_rn(v.z, v.w);
}

// ---------------- K1: mod GEMM (split-K partials, deterministic) --------------
__global__ void k_mod_part(const float* __restrict__ mod,
                           const float* __restrict__ mod_w) {
    __shared__ float sm[B_*256];
    int kc = blockIdx.y;
    int k0 = kc * 256;
    for (int i = threadIdx.x; i < B_*256; i += blockDim.x)
        sm[i] = mod[(i >> 8) * D_ + k0 + (i & 255)];
    __syncthreads();
    int j = blockIdx.x * 128 + threadIdx.x;
    float a0=0.f, a1=0.f, a2=0.f, a3=0.f;
    #pragma unroll 4
    for (int k = 0; k < 256; k++) {
        float w = mod_w[(size_t)(k0 + k) * D3 + j];
        a0 = fmaf(sm[k],       w, a0);
        a1 = fmaf(sm[256 + k], w, a1);
        a2 = fmaf(sm[512 + k], w, a2);
        a3 = fmaf(sm[768 + k], w, a3);
    }
    float* p = g_m3p + (size_t)kc * (B_*D3);
    p[0*D3 + j] = a0; p[1*D3 + j] = a1; p[2*D3 + j] = a2; p[3*D3 + j] = a3;
}

__global__ void k_mod_red(const float* __restrict__ mod_b) {
    int i = blockIdx.x * 256 + threadIdx.x;
    float s = 0.f;
    #pragma unroll
    for (int c = 0; c < KC; c++) s += g_m3p[c * (B_*D3) + i];
    g_m3[i] = s + mod_b[i % D3];
}

// ---------------- K2: LayerNorm + AdaLN modulation (fp16 out) -----------------
__global__ void k_lnmod(const float* __restrict__ x) {
    __shared__ float sh[8];
    int m = blockIdx.x;       // token
    int b = m >> 10;
    int t = threadIdx.x;
    const float* xr = x + (size_t)m * D_;
    float4 v0 = *reinterpret_cast<const float4*>(xr + t*4);
    float4 v1 = *reinterpret_cast<const float4*>(xr + 1024 + t*4);
    float s = v0.x+v0.y+v0.z+v0.w + v1.x+v1.y+v1.z+v1.w;
    s = block_sum<8>(s, sh);
    float mean = s * (1.f / D_);
    float d0=v0.x-mean, d1=v0.y-mean, d2=v0.z-mean, d3=v0.w-mean;
    float d4=v1.x-mean, d5=v1.y-mean, d6=v1.z-mean, d7=v1.w-mean;
    float ss = d0*d0+d1*d1+d2*d2+d3*d3+d4*d4+d5*d5+d6*d6+d7*d7;
    ss = block_sum<8>(ss, sh);
    float rinv = rsqrtf(ss * (1.f / D_) + 1e-6f);
    const float* mb  = g_m3 + b * D3;        // bias
    const float* msc = mb + D_;              // scale
    int e0 = t*4, e1 = 1024 + t*4;
    float o0 = d0*rinv*(1.f+msc[e0+0]) + mb[e0+0];
    float o1 = d1*rinv*(1.f+msc[e0+1]) + mb[e0+1];
    float o2 = d2*rinv*(1.f+msc[e0+2]) + mb[e0+2];
    float o3 = d3*rinv*(1.f+msc[e0+3]) + mb[e0+3];
    float o4 = d4*rinv*(1.f+msc[e1+0]) + mb[e1+0];
    float o5 = d5*rinv*(1.f+msc[e1+1]) + mb[e1+1];
    float o6 = d6*rinv*(1.f+msc[e1+2]) + mb[e1+2];
    float o7 = d7*rinv*(1.f+msc[e1+3]) + mb[e1+3];
    __half* xo = g_xnh + (size_t)m * D_;
    *reinterpret_cast<__half2*>(xo + e0)     = __floats2half2_rn(o0, o1);
    *reinterpret_cast<__half2*>(xo + e0 + 2) = __floats2half2_rn(o2, o3);
    *reinterpret_cast<__half2*>(xo + e1)     = __floats2half2_rn(o4, o5);
    *reinterpret_cast<__half2*>(xo + e1 + 2) = __floats2half2_rn(o6, o7);
}

// ---------------- fp16 WMMA GEMM, 3-stage, BK=32, ONE sync per tile -----------
// 128x128 tile, 4 warps of 64x64.
// EPI=0: C(f32) = A*B                                  (QKV projection)
// EPI=1: Oh(h)  = (A*B) / rowsum(A); full K per CTA    (PV + normalize)
// EPI=2: outp(f32) = (A*B + bb) * gate + xb            (out-proj + final)
template<int EPI>
__global__ void __launch_bounds__(128, 2)
k_gemm3h(const __half* __restrict__ A, int lda, long long sA1, long long sA2,
         const __half* __restrict__ B, int ldb, long long sB1, long long sB2,
         float* __restrict__ C, __half* __restrict__ Oh,
         int ldc, long long sC1, long long sC2,
         int K, int zdiv,
         const float* __restrict__ xb, const float* __restrict__ bb,
         float* __restrict__ outp) {
    constexpr int BM = 128, BN = 128, BK = 32;
    constexpr int AKP = BK + 8;    // 40 halves/row (80 B)
    constexpr int BNP = BN + 8;    // 136 halves/row (272 B)
    constexpr int AS_SZ = BM * AKP;    // 5120 halves
    constexpr int BS_SZ = BK * BNP;    // 4352 halves
    constexpr int STG = AS_SZ + BS_SZ; // 9472 halves per stage
    extern __shared__ __align__(16) char smraw[];
    __half* smem = reinterpret_cast<__half*>(smraw);
    float* scr  = reinterpret_cast<float*>(smraw + 3 * STG * 2);  // 4w x 320 f32
    float* srow = scr + 4 * 320;                                  // 128 f32

    int z  = blockIdx.z;
    int z1 = z / zdiv, z2 = z - z1 * zdiv;
    A += (size_t)(z1 * sA1 + z2 * sA2);
    B += (size_t)(z1 * sB1 + z2 * sB2);
    if (EPI == 0) C  += (size_t)(z1 * sC1 + z2 * sC2);
    if (EPI == 1) Oh += (size_t)(z1 * sC1 + z2 * sC2);

    int tid = threadIdx.x;
    int wid = tid >> 5, lane = tid & 31;
    int wm = wid & 1, wn = wid >> 1;          // 2x2 warps of 64x64
    int bm0 = blockIdx.y * BM, bn0 = blockIdx.x * BN;

    auto load_stage = [&](int kt, int s) {
        __half* As = smem + s * STG;
        __half* Bs = As + AS_SZ;
        #pragma unroll
        for (int it = 0; it < 4; it++) {      // A: 128 rows x 32 halves
            int idx = tid + it * 128;
            int r = idx >> 2, c = (idx & 3) << 3;
            cp_async16(&As[r * AKP + c],
                       A + (size_t)(bm0 + r) * lda + kt + c);
        }
        #pragma unroll
        for (int it = 0; it < 4; it++) {      // B: 32(k) x 128(n) halves
            int idx = tid + it * 128;
            int r = idx >> 4, c = (idx & 15) << 3;
            cp_async16(&Bs[r * BNP + c],
                       B + (size_t)(kt + r) * ldb + bn0 + c);
        }
    };

    wmma::fragment<wmma::accumulator, 16, 16, 16, float> acc[4][4];
    #pragma unroll
    for (int i = 0; i < 4; i++)
        #pragma unroll
        for (int j = 0; j < 4; j++) wmma::fill_fragment(acc[i][j], 0.0f);

    float lsum = 0.f;
    int T = K / BK;
    load_stage(0, 0);  cp_commit();
    load_stage(BK, 1); cp_commit();

    int sbuf = 0;       // stage of tile t (t % 3)
    for (int t = 0; t < T; t++) {
        cp_wait1();
        __syncthreads();
        int nt = t + 2;
        if (nt < T) {
            int ns = sbuf + 2; if (ns >= 3) ns -= 3;
            load_stage(nt * BK, ns);
            cp_commit();
        }
        __half* As = smem + sbuf * STG;
        __half* Bs = As + AS_SZ;
        if (EPI == 1) {                 // thread r sums row r (rotated access)
            const __half* ar = &As[tid * AKP];
            #pragma unroll
            for (int c = 0; c < BK; c++) lsum += __half2float(ar[(tid + c) & 31]);
        }
        #pragma unroll
        for (int ks = 0; ks < BK; ks += 16) {
            wmma::fragment<wmma::matrix_a, 16, 16, 16, __half, wmma::row_major> af[4];
            #pragma unroll
            for (int i = 0; i < 4; i++)
                wmma::load_matrix_sync(af[i], &As[(wm * 64 + i * 16) * AKP + ks], AKP);
            #pragma unroll
            for (int j = 0; j < 4; j++) {
                wmma::fragment<wmma::matrix_b, 16, 16, 16, __half, wmma::row_major> bf;
                wmma::load_matrix_sync(bf, &Bs[ks * BNP + wn * 64 + j * 16], BNP);
                #pragma unroll
                for (int i = 0; i < 4; i++)
                    wmma::mma_sync(acc[i][j], af[i], bf, acc[i][j]);
            }
        }
        if (++sbuf == 3) sbuf = 0;
    }

    float* scrw = scr + wid * 320;   // 16 x 20 f32
    int row = lane >> 1, ch = (lane & 1) * 8;

    if (EPI == 0) {
        #pragma unroll
        for (int i = 0; i < 4; i++)
            #pragma unroll
            for (int j = 0; j < 4; j++)
                wmma::store_matrix_sync(C + (size_t)(bm0 + wm * 64 + i * 16) * ldc + bn0 + wn * 64 + j * 16,
                                        acc[i][j], ldc, wmma::mem_row_major);
    } else if (EPI == 1) {
        // fused normalize: Oh[r, c] = half(acc[r, c] / l[r])
        srow[tid] = lsum;
        __syncthreads();
        #pragma unroll
        for (int i = 0; i < 4; i++) {
            float inv = 1.f / srow[wm * 64 + i * 16 + row];
            #pragma unroll
            for (int j = 0; j < 4; j++) {
                __syncwarp();
                wmma::store_matrix_sync(scrw, acc[i][j], 20, wmma::mem_row_major);
                __syncwarp();
                __align__(16) __half hv[8];
                #pragma unroll
                for (int e = 0; e < 8; e++)
                    hv[e] = __float2half_rn(scrw[row * 20 + ch + e] * inv);
                *reinterpret_cast<uint4*>(
                    &Oh[(size_t)(bm0 + wm * 64 + i * 16 + row) * ldc + bn0 + wn * 64 + j * 16 + ch]) =
                    *reinterpret_cast<uint4*>(hv);
            }
        }
    } else {
        // fused final: outp = (acc + bb) * gate + xb
        #pragma unroll
        for (int i = 0; i < 4; i++) {
            int tok = bm0 + wm * 64 + i * 16 + row;
            const float* gate = g_m3 + (tok >> 10) * D3 + 2 * D_;
            #pragma unroll
            for (int j = 0; j < 4; j++) {
                __syncwarp();
                wmma::store_matrix_sync(scrw, acc[i][j], 20, wmma::mem_row_major);
                __syncwarp();
                int col = bn0 + wn * 64 + j * 16 + ch;
                size_t off = (size_t)tok * D_ + col;
                float4 b0 = *reinterpret_cast<const float4*>(&bb[col]);
                float4 b1 = *reinterpret_cast<const float4*>(&bb[col + 4]);
                float4 gg0 = *reinterpret_cast<const float4*>(&gate[col]);
                float4 gg1 = *reinterpret_cast<const float4*>(&gate[col + 4]);
                float4 x0 = *reinterpret_cast<const float4*>(&xb[off]);
                float4 x1 = *reinterpret_cast<const float4*>(&xb[off + 4]);
                const float* a = &scrw[row * 20 + ch];
                float4 r0, r1;
                r0.x = (a[0] + b0.x) * gg0.x + x0.x;
                r0.y = (a[1] + b0.y) * gg0.y + x0.y;
                r0.z = (a[2] + b0.z) * gg0.z + x0.z;
                r0.w = (a[3] + b0.w) * gg0.w + x0.w;
                r1.x = (a[4] + b1.x) * gg1.x + x1.x;
                r1.y = (a[5] + b1.y) * gg1.y + x1.y;
                r1.z = (a[6] + b1.z) * gg1.z + x1.z;
                r1.w = (a[7] + b1.w) * gg1.w + x1.w;
                *reinterpret_cast<float4*>(&outp[off])     = r0;
                *reinterpret_cast<float4*>(&outp[off + 4]) = r1;
            }
        }
    }
}

static const int SMEM_GH = 3 * 9472 * 2 + (4 * 320 + 128) * 4;  // 62464 bytes

// ---------------- fp16 WMMA GEMM BT + exp epilogue (scores -> E, half) --------
// C[M,N](h) = exp(A[M,K](h) * B[N,K](h)^T - 2); 128x128 tile, 4 warps of 64x64.
__global__ void __launch_bounds__(128, 2)
k_gemmBTexp(const __half* __restrict__ A, int lda, long long sA1,
            const __half* __restrict__ B, int ldb, long long sB1,
            __half*       __restrict__ C, int ldc, long long sC1,
            int K) {
    constexpr int BM = 128, BN = 128, BK = 32;
    constexpr int AKP = BK + 8;        // 40 halves
    constexpr int AS_SZ = BM * AKP;    // 5120 halves
    extern __shared__ __align__(16) char smraw[];
    __half* sh = reinterpret_cast<__half*>(smraw);
    __half* As0 = sh;
    __half* As1 = sh + AS_SZ;
    __half* Bs0 = sh + 2 * AS_SZ;
    __half* Bs1 = sh + 3 * AS_SZ;
    float* scr = reinterpret_cast<float*>(smraw + 4 * AS_SZ * 2);  // 4w x 320 f32

    int z  = blockIdx.z;
    A += (size_t)z * sA1;
    B += (size_t)z * sB1;
    C += (size_t)z * sC1;

    int tid = threadIdx.x;
    int wid = tid >> 5, lane = tid & 31;
    int wm = wid & 1, wn = wid >> 1;
    int bm0 = blockIdx.y * BM, bn0 = blockIdx.x * BN;

    auto load_stage = [&](int kt, int buf) {
        __half* As = buf ? As1 : As0;
        __half* Bs = buf ? Bs1 : Bs0;
        #pragma unroll
        for (int it = 0; it < 4; it++) {
            int idx = tid + it * 128;
            int r = idx >> 2, c = (idx & 3) << 3;
            cp_async16(&As[r * AKP + c],
                       A + (size_t)(bm0 + r) * lda + kt + c);
        }
        #pragma unroll
        for (int it = 0; it < 4; it++) {
            int idx = tid + it * 128;
            int r = idx >> 2, c = (idx & 3) << 3;
            cp_async16(&Bs[r * AKP + c],
                       B + (size_t)(bn0 + r) * ldb + kt + c);
        }
    };

    wmma::fragment<wmma::accumulator, 16, 16, 16, float> acc[4][4];
    #pragma unroll
    for (int i = 0; i < 4; i++)
        #pragma unroll
        for (int j = 0; j < 4; j++) wmma::fill_fragment(acc[i][j], 0.0f);

    int T = K / BK;
    load_stage(0, 0);
    cp_commit();

    for (int t = 0; t < T; t++) {
        if (t + 1 < T) load_stage((t + 1) * BK, (t + 1) & 1);
        cp_commit();
        cp_wait1();
        __syncthreads();
        int buf = t & 1;
        __half* As = buf ? As1 : As0;
        __half* Bs = buf ? Bs1 : Bs0;
        #pragma unroll
        for (int ks = 0; ks < BK; ks += 16) {
            wmma::fragment<wmma::matrix_a, 16, 16, 16, __half, wmma::row_major> af[4];
            #pragma unroll
            for (int i = 0; i < 4; i++)
                wmma::load_matrix_sync(af[i], &As[(wm * 64 + i * 16) * AKP + ks], AKP);
            #pragma unroll
            for (int j = 0; j < 4; j++) {
                wmma::fragment<wmma::matrix_b, 16, 16, 16, __half, wmma::col_major> bf;
                wmma::load_matrix_sync(bf, &Bs[(wn * 64 + j * 16) * AKP + ks], AKP);
                #pragma unroll
                for (int i = 0; i < 4; i++)
                    wmma::mma_sync(acc[i][j], af[i], bf, acc[i][j]);
            }
        }
        __syncthreads();
    }

    // epilogue: per-warp smem staging, exp(x-2), half store
    float* scrw = scr + wid * 320;   // 16 x 20 f32
    int row = lane >> 1, ch = (lane & 1) * 8;
    #pragma unroll
    for (int i = 0; i < 4; i++)
        #pragma unroll
        for (int j = 0; j < 4; j++) {
            __syncwarp();
            wmma::store_matrix_sync(scrw, acc[i][j], 20, wmma::mem_row_major);
            __syncwarp();
            __align__(16) __half hv[8];
            #pragma unroll
            for (int e = 0; e < 8; e++)
                hv[e] = __float2half_rn(__expf(scrw[row * 20 + ch + e] - 2.0f));
            *reinterpret_cast<uint4*>(
                &C[(size_t)(bm0 + wm * 64 + i * 16 + row) * ldc + bn0 + wn * 64 + j * 16 + ch]) =
                *reinterpret_cast<uint4*>(hv);
        }
}

static const int SMEM_BTH = 4 * 5120 * 2 + 4 * 320 * 4;   // 46080

// ---------------- K4: qkv bias + RMSNorm + RoPE -> half [B,H,S,HD] ------------
__global__ void k_qkvpost(const float* __restrict__ qkv_b,
                          const float* __restrict__ cosb,
                          const float* __restrict__ sinb,
                          const float* __restrict__ nqw,
                          const float* __restrict__ nkw) {
    __shared__ float sh4[4];
    __shared__ float bufq[HD_], bufk[HD_];
    int tok = blockIdx.x, h = blockIdx.y, d = threadIdx.x;
    int b = tok >> 10, s = tok & 1023;
    size_t base = (size_t)tok * D3 + h * HD_;
    float qv = g_qkv[base + d]          + qkv_b[h * HD_ + d];
    float kv = g_qkv[base + D_ + d]     + qkv_b[D_ + h * HD_ + d];
    float vv = g_qkv[base + 2*D_ + d]   + qkv_b[2*D_ + h * HD_ + d];
    float sq = block_sum<4>(qv * qv, sh4);
    float sk = block_sum<4>(kv * kv, sh4);
    float rq = rsqrtf(sq * (1.f / HD_) + 1e-6f);
    float rk = rsqrtf(sk * (1.f / HD_) + 1e-6f);
    float qn = qv * rq * nqw[d];
    float kn = kv * rk * nkw[d];
    bufq[d] = qn; bufk[d] = kn;
    __syncthreads();
    float qo = qn, ko = kn;
    if (d < RD_) {
        int i = d >> 1;
        float c  = cosb[s * (RD_/2) + i];
        float sn = sinb[s * (RD_/2) + i];
        if ((d & 1) == 0) { qo = bufq[d] * c - bufq[d+1] * sn;
                            ko = bufk[d] * c - bufk[d+1] * sn; }
        else              { qo = bufq[d-1] * sn + bufq[d] * c;
                            ko = bufk[d-1] * sn + bufk[d] * c; }
    }
    size_t ob = ((size_t)(b * H_ + h) * S_ + s) * HD_ + d;
    g_qh[ob] = __float2half_rn(qo * 0.08838834764831845f);  // 1/sqrt(HD) in Q
    g_kh[ob] = __float2half_rn(ko);
    g_vh[ob] = __float2half_rn(vv);
}

// ---------------- launch ------------------------------------------------------
extern "C" void kernel_launch(void* const* d_in, const int* in_sizes, int n_in,
                              void* d_out, int out_size) {
    const float* x     = (const float*)d_in[0];
    const float* mod   = (const float*)d_in[1];
    const float* cosb  = (const float*)d_in[2];
    const float* sinb  = (const float*)d_in[3];
    const float* qkv_w = (const float*)d_in[4];
    const float* qkv_b = (const float*)d_in[5];
    const float* mod_w = (const float*)d_in[6];
    const float* mod_b = (const float*)d_in[7];
    const float* out_w = (const float*)d_in[8];
    const float* out_b = (const float*)d_in[9];
    const float* nqw   = (const float*)d_in[10];
    const float* nkw   = (const float*)d_in[11];
    float* out = (float*)d_out;

    __half *p_xnh, *p_qh, *p_kh, *p_vh, *p_sh, *p_oh, *p_qkvwh, *p_outwh;
    float *p_qkv;
    cudaGetSymbolAddress((void**)&p_xnh, g_xnh);
    cudaGetSymbolAddress((void**)&p_qkv, g_qkv);
    cudaGetSymbolAddress((void**)&p_qh, g_qh);
    cudaGetSymbolAddress((void**)&p_kh, g_kh);
    cudaGetSymbolAddress((void**)&p_vh, g_vh);
    cudaGetSymbolAddress((void**)&p_sh, g_sh);
    cudaGetSymbolAddress((void**)&p_oh, g_oh);
    cudaGetSymbolAddress((void**)&p_qkvwh, g_qkvwh);
    cudaGetSymbolAddress((void**)&p_outwh, g_outwh);

    cudaFuncSetAttribute(k_gemm3h<0>, cudaFuncAttributeMaxDynamicSharedMemorySize, SMEM_GH);
    cudaFuncSetAttribute(k_gemm3h<1>, cudaFuncAttributeMaxDynamicSharedMemorySize, SMEM_GH);
    cudaFuncSetAttribute(k_gemm3h<2>, cudaFuncAttributeMaxDynamicSharedMemorySize, SMEM_GH);
    cudaFuncSetAttribute(k_gemmBTexp, cudaFuncAttributeMaxDynamicSharedMemorySize, SMEM_BTH);

    // 0) round the big weights to fp16 scratch
    k_round_h<<<(D_*D3)/(4*256), 256>>>(qkv_w, p_qkvwh);
    k_round_h<<<(D_*D_)/(4*256), 256>>>(out_w, p_outwh);
    // 1) m3 = mod @ mod_w + mod_b  (f32 path)
    k_mod_part<<<dim3(D3/128, KC), 128>>>(mod, mod_w);
    k_mod_red<<<(B_*D3)/256, 256>>>(mod_b);
    // 2) xn = modulate(layernorm(x)) -> fp16
    k_lnmod<<<NT, 256>>>(x);
    // 3) qkv = xn @ qkv_w  (fp16 GEMM, f32 out; bias folded into K4)
    k_gemm3h<0><<<dim3(D3/128, NT/128), 128, SMEM_GH>>>(
        p_xnh, D_, 0, 0, p_qkvwh, D3, 0, 0, p_qkv, nullptr, D3, 0, 0,
        D_, 1, nullptr, nullptr, nullptr);
    // 4) bias + rmsnorm + rope -> q,k,v fp16 [B,H,S,HD]
    k_qkvpost<<<dim3(NT, H_), HD_>>>(qkv_b, cosb, sinb, nqw, nkw);
    // 5) E = exp(Q @ K^T - 2) fp16 (bounded: |s|<=11.33 -> E<=1.2e4 < 65504)
    k_gemmBTexp<<<dim3(S_/128, S_/128, B_*H_), 128, SMEM_BTH>>>(
        p_qh, HD_, (long long)S_*HD_,
        p_kh, HD_, (long long)S_*HD_,
        p_sh, S_,  (long long)S_*S_, HD_);
    // 6) O = (E @ V) / rowsum(E) -> fp16 g_oh [B,S,H*HD]; fused normalize
    k_gemm3h<1><<<dim3(1, S_/128, B_*H_), 128, SMEM_GH>>>(
        p_sh, S_,  (long long)H_*S_*S_,  (long long)S_*S_,
        p_vh, HD_, (long long)H_*S_*HD_, (long long)S_*HD_,
        nullptr, p_oh, D_, (long long)S_*D_, (long long)HD_,
        S_, H_, nullptr, nullptr, nullptr);
    // 7) out = (O @ out_w + out_b) * gate + x  (fused final epilogue)
    k_gemm3h<2><<<dim3(D_/128, NT/128), 128, SMEM_GH>>>(
        p_oh, D_, 0, 0, p_outwh, D_, 0, 0, nullptr, nullptr, D_, 0, 0,
        D_, 1, x, out_b, out);
}

// round 15
// speedup vs baseline: 1.0508x; 1.0071x over previous
#include <cuda_runtime.h>
#include <cuda_fp16.h>
#include <mma.h>
#include <cstdint>

using namespace nvcuda;

// Shapes
#define B_  4
#define S_  1024
#define D_  2048
#define H_  16
#define HD_ 128
#define RD_ 64
#define NT  (B_*S_)      // 4096 tokens
#define D3  (3*D_)       // 6144
#define KC  8            // mod-gemm split-K chunks

// ---------------- scratch (static device arrays; allocation-free) -------------
__device__ float  g_m3p[KC*B_*D3];
__device__ float  g_m3[B_*D3];
__device__ __half g_xnh[(size_t)NT*D_];
__device__ __half g_qh[(size_t)B_*H_*S_*HD_];
__device__ __half g_kh[(size_t)B_*H_*S_*HD_];
__device__ __half g_vh[(size_t)B_*H_*S_*HD_];
__device__ __half g_sh[(size_t)B_*H_*S_*S_];   // 128 MB exp(scores-2)
__device__ __half g_oh[(size_t)NT*D_];
__device__ __half g_qkvwh[(size_t)D_*D3];      // fp16 qkv_w
__device__ __half g_outwh[(size_t)D_*D_];      // fp16 out_w

// ---------------- cp.async helpers -------------------------------------------
__device__ __forceinline__ void cp_async16(void* smem_dst, const void* gmem_src) {
    uint32_t s = (uint32_t)__cvta_generic_to_shared(smem_dst);
    asm volatile("cp.async.cg.shared.global [%0], [%1], 16;\n" :: "r"(s), "l"(gmem_src));
}
__device__ __forceinline__ void cp_commit() {
    asm volatile("cp.async.commit_group;\n" ::: "memory");
}
__device__ __forceinline__ void cp_wait1() {
    asm volatile("cp.async.wait_group 1;\n" ::: "memory");
}

// ---------------- helpers ----------------------------------------------------
template<int NW>
__device__ __forceinline__ float block_sum(float v, float* sh) {
    #pragma unroll
    for (int o = 16; o > 0; o >>= 1) v += __shfl_xor_sync(0xffffffffu, v, o);
    int w = threadIdx.x >> 5;
    if ((threadIdx.x & 31) == 0) sh[w] = v;
    __syncthreads();
    float r = 0.f;
    #pragma unroll
    for (int i = 0; i < NW; i++) r += sh[i];
    __syncthreads();
    return r;
}

// ---------------- K0: round weights to fp16 scratch ---------------------------
__global__ void k_round_h(const float* __restrict__ in, __half* __restrict__ o) {
    int i = blockIdx.x * 256 + threadIdx.x;
    float4 v = reinterpret_cast<const float4*>(in)[i];
    __half2* o2 = reinterpret_cast<__half2*>(o);
    o2[2*i]   = __floats2half2_rn(v.x, v.y);
    o2[2*i+1] = __floats2half2_rn(v.z, v.w);
}

// ---------------- K1: mod GEMM (split-K partials, deterministic) --------------
__global__ void k_mod_part(const float* __restrict__ mod,
                           const float* __restrict__ mod_w) {
    __shared__ float sm[B_*256];
    int kc = blockIdx.y;
    int k0 = kc * 256;
    for (int i = threadIdx.x; i < B_*256; i += blockDim.x)
        sm[i] = mod[(i >> 8) * D_ + k0 + (i & 255)];
    __syncthreads();
    int j = blockIdx.x * 128 + threadIdx.x;
    float a0=0.f, a1=0.f, a2=0.f, a3=0.f;
    #pragma unroll 4
    for (int k = 0; k < 256; k++) {
        float w = mod_w[(size_t)(k0 + k) * D3 + j];
        a0 = fmaf(sm[k],       w, a0);
        a1 = fmaf(sm[256 + k], w, a1);
        a2 = fmaf(sm[512 + k], w, a2);
        a3 = fmaf(sm[768 + k], w, a3);
    }
    float* p = g_m3p + (size_t)kc * (B_*D3);
    p[0*D3 + j] = a0; p[1*D3 + j] = a1; p[2*D3 + j] = a2; p[3*D3 + j] = a3;
}

__global__ void k_mod_red(const float* __restrict__ mod_b) {
    int i = blockIdx.x * 256 + threadIdx.x;
    float s = 0.f;
    #pragma unroll
    for (int c = 0; c < KC; c++) s += g_m3p[c * (B_*D3) + i];
    g_m3[i] = s + mod_b[i % D3];
}

// ---------------- K2: LayerNorm + AdaLN modulation (fp16 out) -----------------
__global__ void k_lnmod(const float* __restrict__ x) {
    __shared__ float sh[8];
    int m = blockIdx.x;       // token
    int b = m >> 10;
    int t = threadIdx.x;
    const float* xr = x + (size_t)m * D_;
    float4 v0 = *reinterpret_cast<const float4*>(xr + t*4);
    float4 v1 = *reinterpret_cast<const float4*>(xr + 1024 + t*4);
    float s = v0.x+v0.y+v0.z+v0.w + v1.x+v1.y+v1.z+v1.w;
    s = block_sum<8>(s, sh);
    float mean = s * (1.f / D_);
    float d0=v0.x-mean, d1=v0.y-mean, d2=v0.z-mean, d3=v0.w-mean;
    float d4=v1.x-mean, d5=v1.y-mean, d6=v1.z-mean, d7=v1.w-mean;
    float ss = d0*d0+d1*d1+d2*d2+d3*d3+d4*d4+d5*d5+d6*d6+d7*d7;
    ss = block_sum<8>(ss, sh);
    float rinv = rsqrtf(ss * (1.f / D_) + 1e-6f);
    const float* mb  = g_m3 + b * D3;        // bias
    const float* msc = mb + D_;              // scale
    int e0 = t*4, e1 = 1024 + t*4;
    float o0 = d0*rinv*(1.f+msc[e0+0]) + mb[e0+0];
    float o1 = d1*rinv*(1.f+msc[e0+1]) + mb[e0+1];
    float o2 = d2*rinv*(1.f+msc[e0+2]) + mb[e0+2];
    float o3 = d3*rinv*(1.f+msc[e0+3]) + mb[e0+3];
    float o4 = d4*rinv*(1.f+msc[e1+0]) + mb[e1+0];
    float o5 = d5*rinv*(1.f+msc[e1+1]) + mb[e1+1];
    float o6 = d6*rinv*(1.f+msc[e1+2]) + mb[e1+2];
    float o7 = d7*rinv*(1.f+msc[e1+3]) + mb[e1+3];
    __half* xo = g_xnh + (size_t)m * D_;
    *reinterpret_cast<__half2*>(xo + e0)     = __floats2half2_rn(o0, o1);
    *reinterpret_cast<__half2*>(xo + e0 + 2) = __floats2half2_rn(o2, o3);
    *reinterpret_cast<__half2*>(xo + e1)     = __floats2half2_rn(o4, o5);
    *reinterpret_cast<__half2*>(xo + e1 + 2) = __floats2half2_rn(o6, o7);
}

// ---------------- fp16 WMMA GEMM, 3-stage, BK=32, ONE sync per tile -----------
// 128x128 tile, 4 warps of 64x64.
// EPI=1: Oh(h)  = (A*B) / rowsum(A); full K per CTA    (PV + normalize)
// EPI=2: outp(f32) = (A*B + bb) * gate + xb            (out-proj + final)
// EPI=3: QKV fused: bias + RMSNorm + RoPE -> Qh/Kh/Vh  (N-tile == one head)
template<int EPI>
__global__ void __launch_bounds__(128, 2)
k_gemm3h(const __half* __restrict__ A, int lda, long long sA1, long long sA2,
         const __half* __restrict__ B, int ldb, long long sB1, long long sB2,
         __half* __restrict__ Oh, int ldc, long long sC1, long long sC2,
         int K, int zdiv,
         const float* __restrict__ xb, const float* __restrict__ bb,
         float* __restrict__ outp,
         const float* __restrict__ cosb, const float* __restrict__ sinb,
         const float* __restrict__ nqw, const float* __restrict__ nkw,
         __half* __restrict__ Qh, __half* __restrict__ Kh,
         __half* __restrict__ Vh) {
    constexpr int BM = 128, BN = 128, BK = 32;
    constexpr int AKP = BK + 8;    // 40 halves/row (80 B)
    constexpr int BNP = BN + 8;    // 136 halves/row (272 B)
    constexpr int AS_SZ = BM * AKP;    // 5120 halves
    constexpr int BS_SZ = BK * BNP;    // 4352 halves
    constexpr int STG = AS_SZ + BS_SZ; // 9472 halves per stage
    extern __shared__ __align__(16) char smraw[];
    __half* smem = reinterpret_cast<__half*>(smraw);
    float* scr  = reinterpret_cast<float*>(smraw + 3 * STG * 2);  // 4w x 320 f32
    float* srow = scr + 4 * 320;                                  // 128 f32
    float* ssq  = scr + 4 * 320;                                  // 2 x 128 f32 (EPI=3)

    int z  = blockIdx.z;
    int z1 = z / zdiv, z2 = z - z1 * zdiv;
    A += (size_t)(z1 * sA1 + z2 * sA2);
    B += (size_t)(z1 * sB1 + z2 * sB2);
    if (EPI == 1) Oh += (size_t)(z1 * sC1 + z2 * sC2);

    int tid = threadIdx.x;
    int wid = tid >> 5, lane = tid & 31;
    int wm = wid & 1, wn = wid >> 1;          // 2x2 warps of 64x64
    int bm0 = blockIdx.y * BM, bn0 = blockIdx.x * BN;

    auto load_stage = [&](int kt, int s) {
        __half* As = smem + s * STG;
        __half* Bs = As + AS_SZ;
        #pragma unroll
        for (int it = 0; it < 4; it++) {      // A: 128 rows x 32 halves
            int idx = tid + it * 128;
            int r = idx >> 2, c = (idx & 3) << 3;
            cp_async16(&As[r * AKP + c],
                       A + (size_t)(bm0 + r) * lda + kt + c);
        }
        #pragma unroll
        for (int it = 0; it < 4; it++) {      // B: 32(k) x 128(n) halves
            int idx = tid + it * 128;
            int r = idx >> 4, c = (idx & 15) << 3;
            cp_async16(&Bs[r * BNP + c],
                       B + (size_t)(kt + r) * ldb + bn0 + c);
        }
    };

    wmma::fragment<wmma::accumulator, 16, 16, 16, float> acc[4][4];
    #pragma unroll
    for (int i = 0; i < 4; i++)
        #pragma unroll
        for (int j = 0; j < 4; j++) wmma::fill_fragment(acc[i][j], 0.0f);

    float lsum = 0.f;
    int T = K / BK;
    load_stage(0, 0);  cp_commit();
    load_stage(BK, 1); cp_commit();

    int sbuf = 0;       // stage of tile t (t % 3)
    for (int t = 0; t < T; t++) {
        cp_wait1();
        __syncthreads();
        int nt = t + 2;
        if (nt < T) {
            int ns = sbuf + 2; if (ns >= 3) ns -= 3;
            load_stage(nt * BK, ns);
            cp_commit();
        }
        __half* As = smem + sbuf * STG;
        __half* Bs = As + AS_SZ;
        if (EPI == 1) {                 // thread r sums row r (rotated access)
            const __half* ar = &As[tid * AKP];
            #pragma unroll
            for (int c = 0; c < BK; c++) lsum += __half2float(ar[(tid + c) & 31]);
        }
        #pragma unroll
        for (int ks = 0; ks < BK; ks += 16) {
            wmma::fragment<wmma::matrix_a, 16, 16, 16, __half, wmma::row_major> af[4];
            #pragma unroll
            for (int i = 0; i < 4; i++)
                wmma::load_matrix_sync(af[i], &As[(wm * 64 + i * 16) * AKP + ks], AKP);
            #pragma unroll
            for (int j = 0; j < 4; j++) {
                wmma::fragment<wmma::matrix_b, 16, 16, 16, __half, wmma::row_major> bf;
                wmma::load_matrix_sync(bf, &Bs[ks * BNP + wn * 64 + j * 16], BNP);
                #pragma unroll
                for (int i = 0; i < 4; i++)
                    wmma::mma_sync(acc[i][j], af[i], bf, acc[i][j]);
            }
        }
        if (++sbuf == 3) sbuf = 0;
    }

    float* scrw = scr + wid * 320;   // 16 x 20 f32
    int row = lane >> 1, ch = (lane & 1) * 8;

    if (EPI == 1) {
        // fused normalize: Oh[r, c] = half(acc[r, c] / l[r])
        srow[tid] = lsum;
        __syncthreads();
        #pragma unroll
        for (int i = 0; i < 4; i++) {
            float inv = 1.f / srow[wm * 64 + i * 16 + row];
            #pragma unroll
            for (int j = 0; j < 4; j++) {
                __syncwarp();
                wmma::store_matrix_sync(scrw, acc[i][j], 20, wmma::mem_row_major);
                __syncwarp();
                __align__(16) __half hv[8];
                #pragma unroll
                for (int e = 0; e < 8; e++)
                    hv[e] = __float2half_rn(scrw[row * 20 + ch + e] * inv);
                *reinterpret_cast<uint4*>(
                    &Oh[(size_t)(bm0 + wm * 64 + i * 16 + row) * ldc + bn0 + wn * 64 + j * 16 + ch]) =
                    *reinterpret_cast<uint4*>(hv);
            }
        }
    } else if (EPI == 2) {
        // fused final: outp = (acc + bb) * gate + xb
        #pragma unroll
        for (int i = 0; i < 4; i++) {
            int tok = bm0 + wm * 64 + i * 16 + row;
            const float* gate = g_m3 + (tok >> 10) * D3 + 2 * D_;
            #pragma unroll
            for (int j = 0; j < 4; j++) {
                __syncwarp();
                wmma::store_matrix_sync(scrw, acc[i][j], 20, wmma::mem_row_major);
                __syncwarp();
                int col = bn0 + wn * 64 + j * 16 + ch;
                size_t off = (size_t)tok * D_ + col;
                float4 b0 = *reinterpret_cast<const float4*>(&bb[col]);
                float4 b1 = *reinterpret_cast<const float4*>(&bb[col + 4]);
                float4 gg0 = *reinterpret_cast<const float4*>(&gate[col]);
                float4 gg1 = *reinterpret_cast<const float4*>(&gate[col + 4]);
                float4 x0 = *reinterpret_cast<const float4*>(&xb[off]);
                float4 x1 = *reinterpret_cast<const float4*>(&xb[off + 4]);
                const float* a = &scrw[row * 20 + ch];
                float4 r0, r1;
                r0.x = (a[0] + b0.x) * gg0.x + x0.x;
                r0.y = (a[1] + b0.y) * gg0.y + x0.y;
                r0.z = (a[2] + b0.z) * gg0.z + x0.z;
                r0.w = (a[3] + b0.w) * gg0.w + x0.w;
                r1.x = (a[4] + b1.x) * gg1.x + x1.x;
                r1.y = (a[5] + b1.y) * gg1.y + x1.y;
                r1.z = (a[6] + b1.z) * gg1.z + x1.z;
                r1.w = (a[7] + b1.w) * gg1.w + x1.w;
                *reinterpret_cast<float4*>(&outp[off])     = r0;
                *reinterpret_cast<float4*>(&outp[off + 4]) = r1;
            }
        }
    } else if (EPI == 3) {
        // fused QKV post: tile columns = one head of q/k/v
        int typ  = blockIdx.x >> 4;        // 0=q, 1=k, 2=v
        int head = blockIdx.x & 15;
        const float* bias = bb + bn0;      // qkv_b slice for this tile
        // phase 1: per-row sum of squares of (acc + bias)  [q/k only]
        if (typ < 2) {
            #pragma unroll
            for (int i = 0; i < 4; i++) {
                float p = 0.f;
                #pragma unroll
                for (int j = 0; j < 4; j++) {
                    __syncwarp();
                    wmma::store_matrix_sync(scrw, acc[i][j], 20, wmma::mem_row_major);
                    __syncwarp();
                    int c0 = wn * 64 + j * 16 + ch;
                    #pragma unroll
                    for (int e = 0; e < 8; e++) {
                        float v = scrw[row * 20 + ch + e] + bias[c0 + e];
                        p = fmaf(v, v, p);
                    }
                }
                p += __shfl_xor_sync(0xffffffffu, p, 1);
                if ((lane & 1) == 0)
                    ssq[wn * 128 + wm * 64 + i * 16 + row] = p;
            }
            __syncthreads();
        }
        // phase 2: normalize + rope + store
        __half* dst = (typ == 0) ? Qh : (typ == 1) ? Kh : Vh;
        #pragma unroll
        for (int i = 0; i < 4; i++) {
            int r = wm * 64 + i * 16 + row;
            int tok = bm0 + r;
            int b = tok >> 10, s = tok & 1023;
            float rinv = 0.f;
            if (typ < 2)
                rinv = rsqrtf((ssq[r] + ssq[128 + r]) * (1.f / HD_) + 1e-6f);
            __half* op = dst + ((size_t)(b * H_ + head) * S_ + s) * HD_;
            #pragma unroll
            for (int j = 0; j < 4; j++) {
                __syncwarp();
                wmma::store_matrix_sync(scrw, acc[i][j], 20, wmma::mem_row_major);
                __syncwarp();
                int d0 = wn * 64 + j * 16 + ch;     // head-dim start (mult of 8)
                float n[8];
                #pragma unroll
                for (int e = 0; e < 8; e++) {
                    float v = scrw[row * 20 + ch + e] + bias[d0 + e];
                    if (typ == 0)      n[e] = v * rinv * nqw[d0 + e];
                    else if (typ == 1) n[e] = v * rinv * nkw[d0 + e];
                    else               n[e] = v;
                }
                if (typ < 2 && d0 < RD_) {
                    #pragma unroll
                    for (int p = 0; p < 4; p++) {
                        int i2 = (d0 >> 1) + p;
                        float c  = cosb[s * (RD_/2) + i2];
                        float sn = sinb[s * (RD_/2) + i2];
                        float y0 = n[2*p] * c - n[2*p+1] * sn;
                        float y1 = n[2*p] * sn + n[2*p+1] * c;
                        n[2*p] = y0; n[2*p+1] = y1;
                    }
                }
                __align__(16) __half hv[8];
                #pragma unroll
                for (int e = 0; e < 8; e++)
                    hv[e] = __float2half_rn(typ == 0 ? n[e] * 0.08838834764831845f
                                                     : n[e]);
                *reinterpret_cast<uint4*>(&op[d0]) = *reinterpret_cast<uint4*>(hv);
            }
        }
    }
}

static const int SMEM_GH = 3 * 9472 * 2 + (4 * 320 + 256) * 4;  // 62976 bytes

// ---------------- fp16 WMMA GEMM BT + exp epilogue (scores -> E, half) --------
// C[M,N](h) = exp(A[M,K](h) * B[N,K](h)^T - 2); 128x128 tile, 4 warps of 64x64.
__global__ void __launch_bounds__(128, 2)
k_gemmBTexp(const __half* __restrict__ A, int lda, long long sA1,
            const __half* __restrict__ B, int ldb, long long sB1,
            __half*       __restrict__ C, int ldc, long long sC1,
            int K) {
    constexpr int BM = 128, BN = 128, BK = 32;
    constexpr int AKP = BK + 8;        // 40 halves
    constexpr int AS_SZ = BM * AKP;    // 5120 halves
    extern __shared__ __align__(16) char smraw[];
    __half* sh = reinterpret_cast<__half*>(smraw);
    __half* As0 = sh;
    __half* As1 = sh + AS_SZ;
    __half* Bs0 = sh + 2 * AS_SZ;
    __half* Bs1 = sh + 3 * AS_SZ;
    float* scr = reinterpret_cast<float*>(smraw + 4 * AS_SZ * 2);  // 4w x 320 f32

    int z  = blockIdx.z;
    A += (size_t)z * sA1;
    B += (size_t)z * sB1;
    C += (size_t)z * sC1;

    int tid = threadIdx.x;
    int wid = tid >> 5, lane = tid & 31;
    int wm = wid & 1, wn = wid >> 1;
    int bm0 = blockIdx.y * BM, bn0 = blockIdx.x * BN;

    auto load_stage = [&](int kt, int buf) {
        __half* As = buf ? As1 : As0;
        __half* Bs = buf ? Bs1 : Bs0;
        #pragma unroll
        for (int it = 0; it < 4; it++) {
            int idx = tid + it * 128;
            int r = idx >> 2, c = (idx & 3) << 3;
            cp_async16(&As[r * AKP + c],
                       A + (size_t)(bm0 + r) * lda + kt + c);
        }
        #pragma unroll
        for (int it = 0; it < 4; it++) {
            int idx = tid + it * 128;
            int r = idx >> 2, c = (idx & 3) << 3;
            cp_async16(&Bs[r * AKP + c],
                       B + (size_t)(bn0 + r) * ldb + kt + c);
        }
    };

    wmma::fragment<wmma::accumulator, 16, 16, 16, float> acc[4][4];
    #pragma unroll
    for (int i = 0; i < 4; i++)
        #pragma unroll
        for (int j = 0; j < 4; j++) wmma::fill_fragment(acc[i][j], 0.0f);

    int T = K / BK;
    load_stage(0, 0);
    cp_commit();

    for (int t = 0; t < T; t++) {
        if (t + 1 < T) load_stage((t + 1) * BK, (t + 1) & 1);
        cp_commit();
        cp_wait1();
        __syncthreads();
        int buf = t & 1;
        __half* As = buf ? As1 : As0;
        __half* Bs = buf ? Bs1 : Bs0;
        #pragma unroll
        for (int ks = 0; ks < BK; ks += 16) {
            wmma::fragment<wmma::matrix_a, 16, 16, 16, __half, wmma::row_major> af[4];
            #pragma unroll
            for (int i = 0; i < 4; i++)
                wmma::load_matrix_sync(af[i], &As[(wm * 64 + i * 16) * AKP + ks], AKP);
            #pragma unroll
            for (int j = 0; j < 4; j++) {
                wmma::fragment<wmma::matrix_b, 16, 16, 16, __half, wmma::col_major> bf;
                wmma::load_matrix_sync(bf, &Bs[(wn * 64 + j * 16) * AKP + ks], AKP);
                #pragma unroll
                for (int i = 0; i < 4; i++)
                    wmma::mma_sync(acc[i][j], af[i], bf, acc[i][j]);
            }
        }
        __syncthreads();
    }

    // epilogue: per-warp smem staging, exp(x-2), half store
    float* scrw = scr + wid * 320;   // 16 x 20 f32
    int row = lane >> 1, ch = (lane & 1) * 8;
    #pragma unroll
    for (int i = 0; i < 4; i++)
        #pragma unroll
        for (int j = 0; j < 4; j++) {
            __syncwarp();
            wmma::store_matrix_sync(scrw, acc[i][j], 20, wmma::mem_row_major);
            __syncwarp();
            __align__(16) __half hv[8];
            #pragma unroll
            for (int e = 0; e < 8; e++)
                hv[e] = __float2half_rn(__expf(scrw[row * 20 + ch + e] - 2.0f));
            *reinterpret_cast<uint4*>(
                &C[(size_t)(bm0 + wm * 64 + i * 16 + row) * ldc + bn0 + wn * 64 + j * 16 + ch]) =
                *reinterpret_cast<uint4*>(hv);
        }
}

static const int SMEM_BTH = 4 * 5120 * 2 + 4 * 320 * 4;   // 46080

// ---------------- launch ------------------------------------------------------
extern "C" void kernel_launch(void* const* d_in, const int* in_sizes, int n_in,
                              void* d_out, int out_size) {
    const float* x     = (const float*)d_in[0];
    const float* mod   = (const float*)d_in[1];
    const float* cosb  = (const float*)d_in[2];
    const float* sinb  = (const float*)d_in[3];
    const float* qkv_w = (const float*)d_in[4];
    const float* qkv_b = (const float*)d_in[5];
    const float* mod_w = (const float*)d_in[6];
    const float* mod_b = (const float*)d_in[7];
    const float* out_w = (const float*)d_in[8];
    const float* out_b = (const float*)d_in[9];
    const float* nqw   = (const float*)d_in[10];
    const float* nkw   = (const float*)d_in[11];
    float* out = (float*)d_out;

    __half *p_xnh, *p_qh, *p_kh, *p_vh, *p_sh, *p_oh, *p_qkvwh, *p_outwh;
    cudaGetSymbolAddress((void**)&p_xnh, g_xnh);
    cudaGetSymbolAddress((void**)&p_qh, g_qh);
    cudaGetSymbolAddress((void**)&p_kh, g_kh);
    cudaGetSymbolAddress((void**)&p_vh, g_vh);
    cudaGetSymbolAddress((void**)&p_sh, g_sh);
    cudaGetSymbolAddress((void**)&p_oh, g_oh);
    cudaGetSymbolAddress((void**)&p_qkvwh, g_qkvwh);
    cudaGetSymbolAddress((void**)&p_outwh, g_outwh);

    cudaFuncSetAttribute(k_gemm3h<1>, cudaFuncAttributeMaxDynamicSharedMemorySize, SMEM_GH);
    cudaFuncSetAttribute(k_gemm3h<2>, cudaFuncAttributeMaxDynamicSharedMemorySize, SMEM_GH);
    cudaFuncSetAttribute(k_gemm3h<3>, cudaFuncAttributeMaxDynamicSharedMemorySize, SMEM_GH);
    cudaFuncSetAttribute(k_gemmBTexp, cudaFuncAttributeMaxDynamicSharedMemorySize, SMEM_BTH);

    // 0) round the big weights to fp16 scratch
    k_round_h<<<(D_*D3)/(4*256), 256>>>(qkv_w, p_qkvwh);
    k_round_h<<<(D_*D_)/(4*256), 256>>>(out_w, p_outwh);
    // 1) m3 = mod @ mod_w + mod_b  (f32 path)
    k_mod_part<<<dim3(D3/128, KC), 128>>>(mod, mod_w);
    k_mod_red<<<(B_*D3)/256, 256>>>(mod_b);
    // 2) xn = modulate(layernorm(x)) -> fp16
    k_lnmod<<<NT, 256>>>(x);
    // 3) q,k,v = rmsnorm/rope(xn @ qkv_w + qkv_b) -> fp16, fully fused epilogue
    k_gemm3h<3><<<dim3(D3/128, NT/128), 128, SMEM_GH>>>(
        p_xnh, D_, 0, 0, p_qkvwh, D3, 0, 0, nullptr, 0, 0, 0,
        D_, 1, nullptr, qkv_b, nullptr,
        cosb, sinb, nqw, nkw, p_qh, p_kh, p_vh);
    // 4) E = exp(Q @ K^T - 2) fp16 (bounded: |s|<=11.33 -> E<=1.2e4 < 65504)
    k_gemmBTexp<<<dim3(S_/128, S_/128, B_*H_), 128, SMEM_BTH>>>(
        p_qh, HD_, (long long)S_*HD_,
        p_kh, HD_, (long long)S_*HD_,
        p_sh, S_,  (long long)S_*S_, HD_);
    // 5) O = (E @ V) / rowsum(E) -> fp16 g_oh [B,S,H*HD]; fused normalize
    k_gemm3h<1><<<dim3(1, S_/128, B_*H_), 128, SMEM_GH>>>(
        p_sh, S_,  (long long)H_*S_*S_,  (long long)S_*S_,
        p_vh, HD_, (long long)H_*S_*HD_, (long long)S_*HD_,
        p_oh, D_, (long long)S_*D_, (long long)HD_,
        S_, H_, nullptr, nullptr, nullptr,
        nullptr, nullptr, nullptr, nullptr, nullptr, nullptr, nullptr);
    // 6) out = (O @ out_w + out_b) * gate + x  (fused final epilogue)
    k_gemm3h<2><<<dim3(D_/128, NT/128), 128, SMEM_GH>>>(
        p_oh, D_, 0, 0, p_outwh, D_, 0, 0, nullptr, 0, 0, 0,
        D_, 1, x, out_b, out,
        nullptr, nullptr, nullptr, nullptr, nullptr, nullptr, nullptr);
}